// round 16
// baseline (speedup 1.0000x reference)
#include <cuda_runtime.h>
#include <cuda_fp16.h>
#include <math.h>

#define NN 100000
#define EE 1000000
#define F  64
#define SCAN_B 1024
#define AH 72   // smem row stride in halfs (144B -> conflict-free ldmatrix)

// Scratch (device globals — no allocation allowed)
__device__ __half g_s   [2 * NN * F];   // fp16 dis-scaled messages (pos; neg)
__device__ __half g_h   [2 * NN * F];   // fp16 hidden after PReLU
__device__ __half g_wt16[2 * F * F];    // fp16 W1^T, W2^T  ([n][k] row-major)
__device__ float  g_dis[NN];
__device__ int    g_deg[NN];
__device__ int    g_iperm[NN];
__device__ int    g_off[NN + 1];
__device__ int    g_cursor[NN];
__device__ int    g_bsum[128];
__device__ int    g_scols[EE];
__device__ float  g_sum[F];

__device__ __forceinline__ unsigned h2(float a, float b) {
    __half2 h = __floats2half2_rn(a, b);
    return *(unsigned*)&h;
}
__device__ __forceinline__ void acc_h2(unsigned u, float& a, float& b) {
    float2 f = __half22float2(*(__half2*)&u);
    a += f.x; b += f.y;
}

__device__ __forceinline__ void ldm4(unsigned a[4], unsigned addr) {
    asm volatile("ldmatrix.sync.aligned.m8n8.x4.shared.b16 {%0,%1,%2,%3}, [%4];"
                 : "=r"(a[0]), "=r"(a[1]), "=r"(a[2]), "=r"(a[3]) : "r"(addr));
}
__device__ __forceinline__ void mma16816(float c[4], const unsigned a[4],
                                         unsigned b0, unsigned b1) {
    asm volatile("mma.sync.aligned.m16n8k16.row.col.f32.f16.f16.f32 "
                 "{%0,%1,%2,%3}, {%4,%5,%6,%7}, {%8,%9}, {%0,%1,%2,%3};"
                 : "+f"(c[0]), "+f"(c[1]), "+f"(c[2]), "+f"(c[3])
                 : "r"(a[0]), "r"(a[1]), "r"(a[2]), "r"(a[3]), "r"(b0), "r"(b1));
}

// ---------------------------------------------------------------------------
// Fused init: deg=1 (self-loop), zero g_sum, W1/W2 -> fp16 transposed
// ---------------------------------------------------------------------------
__global__ void k_init(const float* __restrict__ W1, const float* __restrict__ W2, int N) {
    int t = blockIdx.x * blockDim.x + threadIdx.x;
    if (t < N) g_deg[t] = 1;
    if (t < F) g_sum[t] = 0.0f;
    if (t < F * F) {
        int k = t >> 6, c = t & 63;
        g_wt16[c * F + k]         = __float2half_rn(W1[t]);
        g_wt16[F * F + c * F + k] = __float2half_rn(W2[t]);
    }
}

__global__ void k_deg_count(const int* __restrict__ rows, int E) {
    int e = blockIdx.x * blockDim.x + threadIdx.x;
    if (e < E) atomicAdd(&g_deg[rows[e]], 1);
}

// ---------------------------------------------------------------------------
// Scan pass 1 + dis/iperm (fused)
// ---------------------------------------------------------------------------
__global__ void k_scan1(const int* __restrict__ perm, int N) {
    __shared__ int sh[SCAN_B];
    int i = blockIdx.x * SCAN_B + threadIdx.x;
    int dg = (i < N) ? g_deg[i] : 1;
    if (i < N) {
        g_dis[i] = rsqrtf((float)dg);
        g_iperm[perm[i]] = i;
    }
    int v = dg - 1;
    sh[threadIdx.x] = v;
    __syncthreads();
#pragma unroll
    for (int ofs = 1; ofs < SCAN_B; ofs <<= 1) {
        int t = (threadIdx.x >= ofs) ? sh[threadIdx.x - ofs] : 0;
        __syncthreads();
        sh[threadIdx.x] += t;
        __syncthreads();
    }
    if (i < N) g_off[i] = sh[threadIdx.x] - v;
    if (threadIdx.x == SCAN_B - 1) g_bsum[blockIdx.x] = sh[SCAN_B - 1];
}

// ---------------------------------------------------------------------------
// Fused scan passes 2+3: every block redundantly scans the <=128 block sums
// ---------------------------------------------------------------------------
__global__ void k_scan23(int N, int E, int nb) {
    __shared__ int sb[128];
    int t = threadIdx.x;
    if (t < 128) sb[t] = (t < nb) ? g_bsum[t] : 0;
    __syncthreads();
#pragma unroll
    for (int ofs = 1; ofs < 128; ofs <<= 1) {
        int u = (t >= ofs && t < 128) ? sb[t - ofs] : 0;
        __syncthreads();
        if (t < 128) sb[t] += u;
        __syncthreads();
    }
    int add = (blockIdx.x > 0) ? sb[blockIdx.x - 1] : 0;
    int i = blockIdx.x * SCAN_B + t;
    if (i < N) {
        int o = g_off[i] + add;
        g_off[i] = o;
        g_cursor[i] = o;
    }
    if (i == N) g_off[N] = E;
}

__global__ void k_sort(const int* __restrict__ rows, const int* __restrict__ cols, int E) {
    int e = blockIdx.x * blockDim.x + threadIdx.x;
    if (e < E) {
        int slot = atomicAdd(&g_cursor[rows[e]], 1);
        g_scols[slot] = cols[e];
    }
}

// ---------------------------------------------------------------------------
// Tensor-core GEMM via raw mma.sync (m16n8k16), register epilogue.
// W staged to smem; B fragments via ldmatrix.x4 (LDS pipe).
// LAYER 1: A = x fp32; rows pre-scaled by dis -> fp16. Writes g_s pos + neg.
// LAYER 2: A = g_h fp16 (2N rows) raw-copy staging; dis-scale in epilogue.
// Block: 128 threads = 4 warps, tile 64 rows; warp w -> rows w*16..w*16+15.
// ---------------------------------------------------------------------------
template <int LAYER>
__global__ void __launch_bounds__(128) k_gemmw(const float* __restrict__ Aext,
                                               const __half* __restrict__ Wt,
                                               int M, int N) {
    __shared__ __align__(16) __half ahi[64 * AH];
    __shared__ __align__(16) __half ws [64 * AH];

    int tid  = threadIdx.x;
    int lane = tid & 31;
    int wid  = tid >> 5;
    int row0 = blockIdx.x * 64;

    // stage W (64 n-rows x 64 k-halfs) into smem, stride AH
#pragma unroll
    for (int it = 0; it < 4; it++) {
        int idx = it * 128 + tid;
        int r   = idx >> 3;
        int c8  = idx & 7;
        *(uint4*)(ws + r * AH + c8 * 8) = ((const uint4*)(Wt + r * 64))[c8];
    }

    if (LAYER == 1) {
#pragma unroll
        for (int it = 0; it < 8; it++) {
            int idx = it * 128 + tid;
            int r   = idx >> 4;
            int c4  = idx & 15;
            int grow = row0 + r;
            float4 v = make_float4(0.f, 0.f, 0.f, 0.f);
            if (grow < M) {
                v = ((const float4*)(Aext + (size_t)grow * F))[c4];
                float d = g_dis[grow];
                v.x *= d; v.y *= d; v.z *= d; v.w *= d;
            }
            uint2 hi;
            hi.x = h2(v.x, v.y);
            hi.y = h2(v.z, v.w);
            *(uint2*)(ahi + r * AH + c4 * 4) = hi;
        }
    } else {
#pragma unroll
        for (int it = 0; it < 4; it++) {
            int idx = it * 128 + tid;
            int r   = idx >> 3;
            int c8  = idx & 7;
            int grow = row0 + r;
            uint4 v = make_uint4(0u, 0u, 0u, 0u);
            if (grow < M)
                v = ((const uint4*)(g_h + (size_t)grow * F))[c8];
            *(uint4*)(ahi + r * AH + c8 * 8) = v;
        }
    }
    __syncthreads();

    int wr = wid * 16;
    if (row0 + wr >= M) return;
    int g = lane >> 2, t = lane & 3;

    unsigned shi = (unsigned)__cvta_generic_to_shared(ahi);
    unsigned sws = (unsigned)__cvta_generic_to_shared(ws);
    unsigned roff = ((wr + (lane & 15)) * AH + (lane >> 4) * 8) * 2;

    int bm   = lane >> 3;            // 0..3
    int brow = lane & 7;
    unsigned bbase = sws + ((((bm >> 1) * 8 + brow) * AH + (bm & 1) * 8) * 2);

    float c[8][4];
#pragma unroll
    for (int n0 = 0; n0 < 8; n0++)
#pragma unroll
        for (int i = 0; i < 4; i++) c[n0][i] = 0.f;

#pragma unroll
    for (int k0 = 0; k0 < 4; k0++) {
        unsigned ah_[4];
        ldm4(ah_, shi + roff + k0 * 32);
#pragma unroll
        for (int p = 0; p < 4; p++) {
            unsigned bb[4];
            ldm4(bb, bbase + p * 16 * AH * 2 + k0 * 32);
            mma16816(c[p * 2 + 0], ah_, bb[0], bb[1]);
            mma16816(c[p * 2 + 1], ah_, bb[2], bb[3]);
        }
    }

    int r0t = row0 + wr + g;
    int r1t = r0t + 8;
    if (LAYER == 1) {
        if (r0t < M) {
            int j0 = g_iperm[r0t];
            float rn0 = __fdividef(g_dis[j0], g_dis[r0t]);
            __half* p0 = g_s + (size_t)r0t * F + t * 2;
            __half* q0 = g_s + (size_t)(N + j0) * F + t * 2;
#pragma unroll
            for (int n0 = 0; n0 < 8; n0++) {
                *(unsigned*)(p0 + n0 * 8) = h2(c[n0][0], c[n0][1]);
                *(unsigned*)(q0 + n0 * 8) = h2(c[n0][0] * rn0, c[n0][1] * rn0);
            }
        }
        if (r1t < M) {
            int j1 = g_iperm[r1t];
            float rn1 = __fdividef(g_dis[j1], g_dis[r1t]);
            __half* p1 = g_s + (size_t)r1t * F + t * 2;
            __half* q1 = g_s + (size_t)(N + j1) * F + t * 2;
#pragma unroll
            for (int n0 = 0; n0 < 8; n0++) {
                *(unsigned*)(p1 + n0 * 8) = h2(c[n0][2], c[n0][3]);
                *(unsigned*)(q1 + n0 * 8) = h2(c[n0][2] * rn1, c[n0][3] * rn1);
            }
        }
    } else {
        if (r0t < M) {
            float d0 = g_dis[r0t < N ? r0t : r0t - N];
            __half* p0 = g_s + (size_t)r0t * F + t * 2;
#pragma unroll
            for (int n0 = 0; n0 < 8; n0++)
                *(unsigned*)(p0 + n0 * 8) = h2(c[n0][0] * d0, c[n0][1] * d0);
        }
        if (r1t < M) {
            float d1 = g_dis[r1t < N ? r1t : r1t - N];
            __half* p1 = g_s + (size_t)r1t * F + t * 2;
#pragma unroll
            for (int n0 = 0; n0 < 8; n0++)
                *(unsigned*)(p1 + n0 * 8) = h2(c[n0][2] * d1, c[n0][3] * d1);
        }
    }
}

// ---------------------------------------------------------------------------
// CSR gather-aggregate + fused epilogue. One warp per node:
//   lanes 0-15 positive half, lanes 16-31 negative half.
// Unroll-8 main loop (8 outstanding gathers/lane); self-term issued first.
// LAYER 1 writes fp16 hidden state (g_h); LAYER 2 writes fp32 output + summary.
// ---------------------------------------------------------------------------
template <int LAYER>
__global__ void __launch_bounds__(256) k_agg(const float* __restrict__ b,
                                             const float* __restrict__ pa,
                                             float* __restrict__ outext, int N) {
    __shared__ float bs[F];
    int tid = threadIdx.x;
    if (LAYER == 2) {
        if (tid < F) bs[tid] = 0.f;
        __syncthreads();
    }

    int w = (blockIdx.x * blockDim.x + tid) >> 5;
    int lane  = tid & 31;
    int chunk = lane & 15;
    int half  = lane >> 4;

    if (w < N) {
        size_t base = (size_t)half * N * F;
        const __half* sbase = g_s + base + chunk * 4;

        int e0 = g_off[w], e1 = g_off[w + 1];

        // self term issued first (overlaps the first edge batch)
        uint2 vs = *(const uint2*)(sbase + (size_t)w * F);

        float4 a0 = make_float4(0.f, 0.f, 0.f, 0.f);
        float4 a1 = make_float4(0.f, 0.f, 0.f, 0.f);
        float4 a2 = make_float4(0.f, 0.f, 0.f, 0.f);
        float4 a3 = make_float4(0.f, 0.f, 0.f, 0.f);
        int e = e0;
        for (; e + 8 <= e1; e += 8) {
            int c0 = __ldg(&g_scols[e]);
            int c1 = __ldg(&g_scols[e + 1]);
            int c2 = __ldg(&g_scols[e + 2]);
            int c3 = __ldg(&g_scols[e + 3]);
            int c4 = __ldg(&g_scols[e + 4]);
            int c5 = __ldg(&g_scols[e + 5]);
            int c6 = __ldg(&g_scols[e + 6]);
            int c7 = __ldg(&g_scols[e + 7]);
            uint2 v0 = *(const uint2*)(sbase + (size_t)c0 * F);
            uint2 v1 = *(const uint2*)(sbase + (size_t)c1 * F);
            uint2 v2 = *(const uint2*)(sbase + (size_t)c2 * F);
            uint2 v3 = *(const uint2*)(sbase + (size_t)c3 * F);
            uint2 v4 = *(const uint2*)(sbase + (size_t)c4 * F);
            uint2 v5 = *(const uint2*)(sbase + (size_t)c5 * F);
            uint2 v6 = *(const uint2*)(sbase + (size_t)c6 * F);
            uint2 v7 = *(const uint2*)(sbase + (size_t)c7 * F);
            acc_h2(v0.x, a0.x, a0.y); acc_h2(v0.y, a0.z, a0.w);
            acc_h2(v1.x, a1.x, a1.y); acc_h2(v1.y, a1.z, a1.w);
            acc_h2(v2.x, a2.x, a2.y); acc_h2(v2.y, a2.z, a2.w);
            acc_h2(v3.x, a3.x, a3.y); acc_h2(v3.y, a3.z, a3.w);
            acc_h2(v4.x, a0.x, a0.y); acc_h2(v4.y, a0.z, a0.w);
            acc_h2(v5.x, a1.x, a1.y); acc_h2(v5.y, a1.z, a1.w);
            acc_h2(v6.x, a2.x, a2.y); acc_h2(v6.y, a2.z, a2.w);
            acc_h2(v7.x, a3.x, a3.y); acc_h2(v7.y, a3.z, a3.w);
        }
        if (e + 4 <= e1) {
            int c0 = __ldg(&g_scols[e]);
            int c1 = __ldg(&g_scols[e + 1]);
            int c2 = __ldg(&g_scols[e + 2]);
            int c3 = __ldg(&g_scols[e + 3]);
            uint2 v0 = *(const uint2*)(sbase + (size_t)c0 * F);
            uint2 v1 = *(const uint2*)(sbase + (size_t)c1 * F);
            uint2 v2 = *(const uint2*)(sbase + (size_t)c2 * F);
            uint2 v3 = *(const uint2*)(sbase + (size_t)c3 * F);
            acc_h2(v0.x, a0.x, a0.y); acc_h2(v0.y, a0.z, a0.w);
            acc_h2(v1.x, a1.x, a1.y); acc_h2(v1.y, a1.z, a1.w);
            acc_h2(v2.x, a2.x, a2.y); acc_h2(v2.y, a2.z, a2.w);
            acc_h2(v3.x, a3.x, a3.y); acc_h2(v3.y, a3.z, a3.w);
            e += 4;
        }
        if (e + 2 <= e1) {
            int c0 = __ldg(&g_scols[e]);
            int c1 = __ldg(&g_scols[e + 1]);
            uint2 v0 = *(const uint2*)(sbase + (size_t)c0 * F);
            uint2 v1 = *(const uint2*)(sbase + (size_t)c1 * F);
            acc_h2(v0.x, a0.x, a0.y); acc_h2(v0.y, a0.z, a0.w);
            acc_h2(v1.x, a1.x, a1.y); acc_h2(v1.y, a1.z, a1.w);
            e += 2;
        }
        if (e < e1) {
            int c0 = __ldg(&g_scols[e]);
            uint2 v0 = *(const uint2*)(sbase + (size_t)c0 * F);
            acc_h2(v0.x, a0.x, a0.y); acc_h2(v0.y, a0.z, a0.w);
        }
        acc_h2(vs.x, a2.x, a2.y); acc_h2(vs.y, a2.z, a2.w);

        a0.x += a1.x; a0.y += a1.y; a0.z += a1.z; a0.w += a1.w;
        a2.x += a3.x; a2.y += a3.y; a2.z += a3.z; a2.w += a3.w;
        a0.x += a2.x; a0.y += a2.y; a0.z += a2.z; a0.w += a2.w;

        float d = g_dis[w];
        float4 bv = ((const float4*)b)[chunk];
        float4 r;
        r.x = fmaf(d, a0.x, bv.x);
        r.y = fmaf(d, a0.y, bv.y);
        r.z = fmaf(d, a0.z, bv.z);
        r.w = fmaf(d, a0.w, bv.w);

        size_t off = base + (size_t)w * F + chunk * 4;
        if (LAYER == 1) {
            float a = pa[0];
            r.x = (r.x >= 0.f) ? r.x : a * r.x;
            r.y = (r.y >= 0.f) ? r.y : a * r.y;
            r.z = (r.z >= 0.f) ? r.z : a * r.z;
            r.w = (r.w >= 0.f) ? r.w : a * r.w;
            uint2 hw;
            hw.x = h2(r.x, r.y);
            hw.y = h2(r.z, r.w);
            *((uint2*)(g_h + off)) = hw;
        } else {
            *((float4*)(outext + off)) = r;
            if (half == 0) {
                atomicAdd(&bs[chunk * 4 + 0], r.x);
                atomicAdd(&bs[chunk * 4 + 1], r.y);
                atomicAdd(&bs[chunk * 4 + 2], r.z);
                atomicAdd(&bs[chunk * 4 + 3], r.w);
            }
        }
    }

    if (LAYER == 2) {
        __syncthreads();
        if (tid < F) atomicAdd(&g_sum[tid], bs[tid]);
    }
}

// ---------------------------------------------------------------------------
__global__ void k_summary(float* __restrict__ out, int N) {
    int c = threadIdx.x;
    if (c < F) {
        float m = g_sum[c] / (float)N;
        out[c] = 1.0f / (1.0f + expf(-m));
    }
}

// ---------------------------------------------------------------------------
extern "C" void kernel_launch(void* const* d_in, const int* in_sizes, int n_in,
                              void* d_out, int out_size) {
    const float* x    = (const float*)d_in[0];
    const int*   ei   = (const int*)  d_in[1];
    const int*   perm = (const int*)  d_in[2];
    const float* W1   = (const float*)d_in[3];
    const float* b1   = (const float*)d_in[4];
    const float* pa   = (const float*)d_in[5];
    const float* W2   = (const float*)d_in[6];
    const float* b2   = (const float*)d_in[7];

    int N = in_sizes[0] / F;
    int E = in_sizes[1] / 2;
    const int* rows = ei;
    const int* cols = ei + E;
    float* out = (float*)d_out;

    const int T = 256;
    int gN = (N + T - 1) / T;
    int gE = (E + T - 1) / T;
    int nb = (N + SCAN_B - 1) / SCAN_B;
    int gAgg = (N * 32 + T - 1) / T;

    __half* wt1 = nullptr, *wt2 = nullptr;
    cudaGetSymbolAddress((void**)&wt1, g_wt16);
    wt2 = wt1 + F * F;

    cudaStream_t s2;
    cudaStreamCreateWithFlags(&s2, cudaStreamNonBlocking);
    cudaEvent_t evA, evB;
    cudaEventCreateWithFlags(&evA, cudaEventDisableTiming);
    cudaEventCreateWithFlags(&evB, cudaEventDisableTiming);

    // serial prefix: init / degrees / scan1 (dis + iperm)
    k_init<<<gN, T>>>(W1, W2, N);
    k_deg_count<<<gE, T>>>(rows, E);
    k_scan1<<<nb, SCAN_B>>>(perm, N);

    // fork: GEMM1 on s2 || CSR-build tail on main
    cudaEventRecord(evA, 0);
    cudaStreamWaitEvent(s2, evA, 0);
    k_gemmw<1><<<(N + 63) / 64, 128, 0, s2>>>(x, wt1, N, N);
    cudaEventRecord(evB, s2);

    k_scan23<<<nb + 1, SCAN_B>>>(N, E, nb);
    k_sort<<<gE, T>>>(rows, cols, E);

    // join
    cudaStreamWaitEvent(0, evB, 0);

    // aggregate layer 1 -> fp16 hidden
    k_agg<1><<<gAgg, T>>>(b1, pa, nullptr, N);

    // layer 2
    k_gemmw<2><<<(2 * N + 63) / 64, 128>>>(nullptr, wt2, 2 * N, N);
    k_agg<2><<<gAgg, T>>>(b2, pa, out, N);

    // summary
    k_summary<<<1, 64>>>(out + (size_t)2 * N * F, N);
}

// round 17
// speedup vs baseline: 1.0772x; 1.0772x over previous
#include <cuda_runtime.h>
#include <cuda_fp16.h>
#include <math.h>

#define NN 100000
#define EE 1000000
#define F  64
#define SCAN_B 1024
#define AH 72   // smem row stride in halfs (144B -> conflict-free ldmatrix)

// Scratch (device globals — no allocation allowed)
__device__ __half g_s   [2 * NN * F];   // fp16 dis-scaled messages (pos; neg)
__device__ __half g_h   [2 * NN * F];   // fp16 dis*hidden after PReLU
__device__ __half g_wt16[2 * F * F];    // fp16 W1^T, W2^T  ([n][k] row-major)
__device__ float  g_dis[NN];
__device__ int    g_deg[NN];
__device__ int    g_iperm[NN];
__device__ int    g_off[NN + 1];
__device__ int    g_cursor[NN];
__device__ int    g_bsum[128];
__device__ int    g_scols[EE];
__device__ float  g_sum[F];

__device__ __forceinline__ unsigned h2(float a, float b) {
    __half2 h = __floats2half2_rn(a, b);
    return *(unsigned*)&h;
}
__device__ __forceinline__ void acc_h2(unsigned u, float& a, float& b) {
    float2 f = __half22float2(*(__half2*)&u);
    a += f.x; b += f.y;
}

__device__ __forceinline__ void ldm4(unsigned a[4], unsigned addr) {
    asm volatile("ldmatrix.sync.aligned.m8n8.x4.shared.b16 {%0,%1,%2,%3}, [%4];"
                 : "=r"(a[0]), "=r"(a[1]), "=r"(a[2]), "=r"(a[3]) : "r"(addr));
}
__device__ __forceinline__ void mma16816(float c[4], const unsigned a[4],
                                         unsigned b0, unsigned b1) {
    asm volatile("mma.sync.aligned.m16n8k16.row.col.f32.f16.f16.f32 "
                 "{%0,%1,%2,%3}, {%4,%5,%6,%7}, {%8,%9}, {%0,%1,%2,%3};"
                 : "+f"(c[0]), "+f"(c[1]), "+f"(c[2]), "+f"(c[3])
                 : "r"(a[0]), "r"(a[1]), "r"(a[2]), "r"(a[3]), "r"(b0), "r"(b1));
}

// ---------------------------------------------------------------------------
// Fused init: deg=1 (self-loop), zero g_sum, W1/W2 -> fp16 transposed
// ---------------------------------------------------------------------------
__global__ void k_init(const float* __restrict__ W1, const float* __restrict__ W2, int N) {
    int t = blockIdx.x * blockDim.x + threadIdx.x;
    if (t < N) g_deg[t] = 1;
    if (t < F) g_sum[t] = 0.0f;
    if (t < F * F) {
        int k = t >> 6, c = t & 63;
        g_wt16[c * F + k]         = __float2half_rn(W1[t]);
        g_wt16[F * F + c * F + k] = __float2half_rn(W2[t]);
    }
}

__global__ void k_deg_count(const int* __restrict__ rows, int E) {
    int e = blockIdx.x * blockDim.x + threadIdx.x;
    if (e < E) atomicAdd(&g_deg[rows[e]], 1);
}

// dis + iperm only (feeds GEMM1's stream; scan runs concurrently on main)
__global__ void k_dis(const int* __restrict__ perm, int N) {
    int i = blockIdx.x * blockDim.x + threadIdx.x;
    if (i < N) {
        g_dis[i] = rsqrtf((float)g_deg[i]);
        g_iperm[perm[i]] = i;
    }
}

// ---------------------------------------------------------------------------
// Scan pass 1: block-local exclusive scan of (deg-1)
// ---------------------------------------------------------------------------
__global__ void k_scan1(int N) {
    __shared__ int sh[SCAN_B];
    int i = blockIdx.x * SCAN_B + threadIdx.x;
    int v = (i < N) ? (g_deg[i] - 1) : 0;
    sh[threadIdx.x] = v;
    __syncthreads();
#pragma unroll
    for (int ofs = 1; ofs < SCAN_B; ofs <<= 1) {
        int t = (threadIdx.x >= ofs) ? sh[threadIdx.x - ofs] : 0;
        __syncthreads();
        sh[threadIdx.x] += t;
        __syncthreads();
    }
    if (i < N) g_off[i] = sh[threadIdx.x] - v;
    if (threadIdx.x == SCAN_B - 1) g_bsum[blockIdx.x] = sh[SCAN_B - 1];
}

// ---------------------------------------------------------------------------
// Fused scan passes 2+3: every block redundantly scans the <=128 block sums
// ---------------------------------------------------------------------------
__global__ void k_scan23(int N, int E, int nb) {
    __shared__ int sb[128];
    int t = threadIdx.x;
    if (t < 128) sb[t] = (t < nb) ? g_bsum[t] : 0;
    __syncthreads();
#pragma unroll
    for (int ofs = 1; ofs < 128; ofs <<= 1) {
        int u = (t >= ofs && t < 128) ? sb[t - ofs] : 0;
        __syncthreads();
        if (t < 128) sb[t] += u;
        __syncthreads();
    }
    int add = (blockIdx.x > 0) ? sb[blockIdx.x - 1] : 0;
    int i = blockIdx.x * SCAN_B + t;
    if (i < N) {
        int o = g_off[i] + add;
        g_off[i] = o;
        g_cursor[i] = o;
    }
    if (i == N) g_off[N] = E;
}

__global__ void k_sort(const int* __restrict__ rows, const int* __restrict__ cols, int E) {
    int e = blockIdx.x * blockDim.x + threadIdx.x;
    if (e < E) {
        int slot = atomicAdd(&g_cursor[rows[e]], 1);
        g_scols[slot] = cols[e];
    }
}

// ---------------------------------------------------------------------------
// Tensor-core GEMM via raw mma.sync (m16n8k16), register epilogue.
// W staged to smem; B fragments via ldmatrix.x4 (LDS pipe).
// LAYER 1: A = x fp32; rows pre-scaled by dis -> fp16. Writes g_s pos + neg.
// LAYER 2: A = g_h fp16 (= dis*h, 2N rows) raw-copy staging; epilogue is a
//          pure pack (dis already folded into h by agg1).
// Block: 128 threads = 4 warps, tile 64 rows; warp w -> rows w*16..w*16+15.
// ---------------------------------------------------------------------------
template <int LAYER>
__global__ void __launch_bounds__(128) k_gemmw(const float* __restrict__ Aext,
                                               const __half* __restrict__ Wt,
                                               int M, int N) {
    __shared__ __align__(16) __half ahi[64 * AH];
    __shared__ __align__(16) __half ws [64 * AH];

    int tid  = threadIdx.x;
    int lane = tid & 31;
    int wid  = tid >> 5;
    int row0 = blockIdx.x * 64;

    // stage W (64 n-rows x 64 k-halfs) into smem, stride AH
#pragma unroll
    for (int it = 0; it < 4; it++) {
        int idx = it * 128 + tid;
        int r   = idx >> 3;
        int c8  = idx & 7;
        *(uint4*)(ws + r * AH + c8 * 8) = ((const uint4*)(Wt + r * 64))[c8];
    }

    if (LAYER == 1) {
#pragma unroll
        for (int it = 0; it < 8; it++) {
            int idx = it * 128 + tid;
            int r   = idx >> 4;
            int c4  = idx & 15;
            int grow = row0 + r;
            float4 v = make_float4(0.f, 0.f, 0.f, 0.f);
            if (grow < M) {
                v = ((const float4*)(Aext + (size_t)grow * F))[c4];
                float d = g_dis[grow];
                v.x *= d; v.y *= d; v.z *= d; v.w *= d;
            }
            uint2 hi;
            hi.x = h2(v.x, v.y);
            hi.y = h2(v.z, v.w);
            *(uint2*)(ahi + r * AH + c4 * 4) = hi;
        }
    } else {
#pragma unroll
        for (int it = 0; it < 4; it++) {
            int idx = it * 128 + tid;
            int r   = idx >> 3;
            int c8  = idx & 7;
            int grow = row0 + r;
            uint4 v = make_uint4(0u, 0u, 0u, 0u);
            if (grow < M)
                v = ((const uint4*)(g_h + (size_t)grow * F))[c8];
            *(uint4*)(ahi + r * AH + c8 * 8) = v;
        }
    }
    __syncthreads();

    int wr = wid * 16;
    if (row0 + wr >= M) return;
    int g = lane >> 2, t = lane & 3;

    unsigned shi = (unsigned)__cvta_generic_to_shared(ahi);
    unsigned sws = (unsigned)__cvta_generic_to_shared(ws);
    unsigned roff = ((wr + (lane & 15)) * AH + (lane >> 4) * 8) * 2;

    int bm   = lane >> 3;            // 0..3
    int brow = lane & 7;
    unsigned bbase = sws + ((((bm >> 1) * 8 + brow) * AH + (bm & 1) * 8) * 2);

    float c[8][4];
#pragma unroll
    for (int n0 = 0; n0 < 8; n0++)
#pragma unroll
        for (int i = 0; i < 4; i++) c[n0][i] = 0.f;

#pragma unroll
    for (int k0 = 0; k0 < 4; k0++) {
        unsigned ah_[4];
        ldm4(ah_, shi + roff + k0 * 32);
#pragma unroll
        for (int p = 0; p < 4; p++) {
            unsigned bb[4];
            ldm4(bb, bbase + p * 16 * AH * 2 + k0 * 32);
            mma16816(c[p * 2 + 0], ah_, bb[0], bb[1]);
            mma16816(c[p * 2 + 1], ah_, bb[2], bb[3]);
        }
    }

    int r0t = row0 + wr + g;
    int r1t = r0t + 8;
    if (LAYER == 1) {
        if (r0t < M) {
            int j0 = g_iperm[r0t];
            float rn0 = __fdividef(g_dis[j0], g_dis[r0t]);
            __half* p0 = g_s + (size_t)r0t * F + t * 2;
            __half* q0 = g_s + (size_t)(N + j0) * F + t * 2;
#pragma unroll
            for (int n0 = 0; n0 < 8; n0++) {
                *(unsigned*)(p0 + n0 * 8) = h2(c[n0][0], c[n0][1]);
                *(unsigned*)(q0 + n0 * 8) = h2(c[n0][0] * rn0, c[n0][1] * rn0);
            }
        }
        if (r1t < M) {
            int j1 = g_iperm[r1t];
            float rn1 = __fdividef(g_dis[j1], g_dis[r1t]);
            __half* p1 = g_s + (size_t)r1t * F + t * 2;
            __half* q1 = g_s + (size_t)(N + j1) * F + t * 2;
#pragma unroll
            for (int n0 = 0; n0 < 8; n0++) {
                *(unsigned*)(p1 + n0 * 8) = h2(c[n0][2], c[n0][3]);
                *(unsigned*)(q1 + n0 * 8) = h2(c[n0][2] * rn1, c[n0][3] * rn1);
            }
        }
    } else {
        if (r0t < M) {
            __half* p0 = g_s + (size_t)r0t * F + t * 2;
#pragma unroll
            for (int n0 = 0; n0 < 8; n0++)
                *(unsigned*)(p0 + n0 * 8) = h2(c[n0][0], c[n0][1]);
        }
        if (r1t < M) {
            __half* p1 = g_s + (size_t)r1t * F + t * 2;
#pragma unroll
            for (int n0 = 0; n0 < 8; n0++)
                *(unsigned*)(p1 + n0 * 8) = h2(c[n0][2], c[n0][3]);
        }
    }
}

// ---------------------------------------------------------------------------
// CSR gather-aggregate + fused epilogue. One warp per node:
//   lanes 0-15 positive half, lanes 16-31 negative half. MLP=4 unroll.
// LAYER 1 writes fp16 dis*hidden (g_h); LAYER 2 writes fp32 output + summary.
// ---------------------------------------------------------------------------
template <int LAYER>
__global__ void __launch_bounds__(256) k_agg(const float* __restrict__ b,
                                             const float* __restrict__ pa,
                                             float* __restrict__ outext, int N) {
    __shared__ float bs[F];
    int tid = threadIdx.x;
    if (LAYER == 2) {
        if (tid < F) bs[tid] = 0.f;
        __syncthreads();
    }

    int w = (blockIdx.x * blockDim.x + tid) >> 5;
    int lane  = tid & 31;
    int chunk = lane & 15;
    int half  = lane >> 4;

    if (w < N) {
        size_t base = (size_t)half * N * F;
        const __half* sbase = g_s + base + chunk * 4;

        int e0 = g_off[w], e1 = g_off[w + 1];
        float4 a0 = make_float4(0.f, 0.f, 0.f, 0.f);
        float4 a1 = make_float4(0.f, 0.f, 0.f, 0.f);
        int e = e0;
        for (; e + 4 <= e1; e += 4) {
            int c0 = __ldg(&g_scols[e]);
            int c1 = __ldg(&g_scols[e + 1]);
            int c2 = __ldg(&g_scols[e + 2]);
            int c3 = __ldg(&g_scols[e + 3]);
            uint2 v0 = *(const uint2*)(sbase + (size_t)c0 * F);
            uint2 v1 = *(const uint2*)(sbase + (size_t)c1 * F);
            uint2 v2 = *(const uint2*)(sbase + (size_t)c2 * F);
            uint2 v3 = *(const uint2*)(sbase + (size_t)c3 * F);
            acc_h2(v0.x, a0.x, a0.y); acc_h2(v0.y, a0.z, a0.w);
            acc_h2(v1.x, a1.x, a1.y); acc_h2(v1.y, a1.z, a1.w);
            acc_h2(v2.x, a0.x, a0.y); acc_h2(v2.y, a0.z, a0.w);
            acc_h2(v3.x, a1.x, a1.y); acc_h2(v3.y, a1.z, a1.w);
        }
        if (e + 2 <= e1) {
            int c0 = __ldg(&g_scols[e]);
            int c1 = __ldg(&g_scols[e + 1]);
            uint2 v0 = *(const uint2*)(sbase + (size_t)c0 * F);
            uint2 v1 = *(const uint2*)(sbase + (size_t)c1 * F);
            acc_h2(v0.x, a0.x, a0.y); acc_h2(v0.y, a0.z, a0.w);
            acc_h2(v1.x, a1.x, a1.y); acc_h2(v1.y, a1.z, a1.w);
            e += 2;
        }
        if (e < e1) {
            int c0 = __ldg(&g_scols[e]);
            uint2 v0 = *(const uint2*)(sbase + (size_t)c0 * F);
            acc_h2(v0.x, a0.x, a0.y); acc_h2(v0.y, a0.z, a0.w);
        }
        // self term
        uint2 vs = *(const uint2*)(sbase + (size_t)w * F);
        acc_h2(vs.x, a0.x, a0.y); acc_h2(vs.y, a0.z, a0.w);

        a0.x += a1.x; a0.y += a1.y; a0.z += a1.z; a0.w += a1.w;

        float d = g_dis[w];
        float4 bv = ((const float4*)b)[chunk];
        float4 r;
        r.x = fmaf(d, a0.x, bv.x);
        r.y = fmaf(d, a0.y, bv.y);
        r.z = fmaf(d, a0.z, bv.z);
        r.w = fmaf(d, a0.w, bv.w);

        size_t off = base + (size_t)w * F + chunk * 4;
        if (LAYER == 1) {
            float a = pa[0];
            r.x = (r.x >= 0.f) ? r.x : a * r.x;
            r.y = (r.y >= 0.f) ? r.y : a * r.y;
            r.z = (r.z >= 0.f) ? r.z : a * r.z;
            r.w = (r.w >= 0.f) ? r.w : a * r.w;
            // fold destination dis into hidden: (d*h)@W2 = d*(h@W2)
            uint2 hw;
            hw.x = h2(r.x * d, r.y * d);
            hw.y = h2(r.z * d, r.w * d);
            *((uint2*)(g_h + off)) = hw;
        } else {
            *((float4*)(outext + off)) = r;
            if (half == 0) {
                atomicAdd(&bs[chunk * 4 + 0], r.x);
                atomicAdd(&bs[chunk * 4 + 1], r.y);
                atomicAdd(&bs[chunk * 4 + 2], r.z);
                atomicAdd(&bs[chunk * 4 + 3], r.w);
            }
        }
    }

    if (LAYER == 2) {
        __syncthreads();
        if (tid < F) atomicAdd(&g_sum[tid], bs[tid]);
    }
}

// ---------------------------------------------------------------------------
__global__ void k_summary(float* __restrict__ out, int N) {
    int c = threadIdx.x;
    if (c < F) {
        float m = g_sum[c] / (float)N;
        out[c] = 1.0f / (1.0f + expf(-m));
    }
}

// ---------------------------------------------------------------------------
extern "C" void kernel_launch(void* const* d_in, const int* in_sizes, int n_in,
                              void* d_out, int out_size) {
    const float* x    = (const float*)d_in[0];
    const int*   ei   = (const int*)  d_in[1];
    const int*   perm = (const int*)  d_in[2];
    const float* W1   = (const float*)d_in[3];
    const float* b1   = (const float*)d_in[4];
    const float* pa   = (const float*)d_in[5];
    const float* W2   = (const float*)d_in[6];
    const float* b2   = (const float*)d_in[7];

    int N = in_sizes[0] / F;
    int E = in_sizes[1] / 2;
    const int* rows = ei;
    const int* cols = ei + E;
    float* out = (float*)d_out;

    const int T = 256;
    int gN = (N + T - 1) / T;
    int gE = (E + T - 1) / T;
    int nb = (N + SCAN_B - 1) / SCAN_B;
    int gAgg = (N * 32 + T - 1) / T;

    __half* wt1 = nullptr, *wt2 = nullptr;
    cudaGetSymbolAddress((void**)&wt1, g_wt16);
    wt2 = wt1 + F * F;

    cudaStream_t s2;
    cudaStreamCreateWithFlags(&s2, cudaStreamNonBlocking);
    cudaEvent_t evA, evB;
    cudaEventCreateWithFlags(&evA, cudaEventDisableTiming);
    cudaEventCreateWithFlags(&evB, cudaEventDisableTiming);

    // serial prefix: init / degrees
    k_init<<<gN, T>>>(W1, W2, N);
    k_deg_count<<<gE, T>>>(rows, E);

    // fork: (dis/iperm -> GEMM1) on s2 || full scan/sort chain on main
    cudaEventRecord(evA, 0);
    cudaStreamWaitEvent(s2, evA, 0);
    k_dis<<<gN, T, 0, s2>>>(perm, N);
    k_gemmw<1><<<(N + 63) / 64, 128, 0, s2>>>(x, wt1, N, N);
    cudaEventRecord(evB, s2);

    k_scan1<<<nb, SCAN_B>>>(N);
    k_scan23<<<nb + 1, SCAN_B>>>(N, E, nb);
    k_sort<<<gE, T>>>(rows, cols, E);

    // join
    cudaStreamWaitEvent(0, evB, 0);

    // aggregate layer 1 -> fp16 dis*hidden
    k_agg<1><<<gAgg, T>>>(b1, pa, nullptr, N);

    // layer 2
    k_gemmw<2><<<(2 * N + 63) / 64, 128>>>(nullptr, wt2, 2 * N, N);
    k_agg<2><<<gAgg, T>>>(b2, pa, out, N);

    // summary
    k_summary<<<1, 64>>>(out + (size_t)2 * N * F, N);
}